// round 2
// baseline (speedup 1.0000x reference)
#include <cuda_runtime.h>
#include <cstdint>
#include <math.h>

#define BDIM 256
#define LATD 20
#define HID 128
#define GDIM 25000
#define CDIM 7
#define GBD 1000

// Output layout (float32, flattened tuple in order):
//   mu      [256,25000]    @ 0
//   theta   [256,25000]    @ 6400000
//   pi_drop [256,25000]    @ 12800000
//   sample  [256,25000]    @ 19200000
//   pi      [256,25000,7]  @ 25600000
#define OFF_THETA  6400000
#define OFF_PDROP 12800000
#define OFF_SAMP  19200000
#define OFF_PI    25600000

// Scratch (device globals: no allocation allowed)
__device__ float g_xT[HID * BDIM];          // x transposed: [h][b]
__device__ float g_rlog[CDIM * BDIM * GBD]; // rho logits [c][b][o]
__device__ float g_pi[BDIM * GBD * CDIM];   // softmax(rho) as [b][o][c]
__device__ float g_lpi[BDIM * GBD * CDIM];  // log(pi + 1e-20) as [b][o][c]

// ---------------------------------------------------------------------------
// JAX threefry2x32, key = (0, 42), 20 rounds.
// Partitionable mode (JAX >= 0.5 default): per element i,
//   (o0, o1) = threefry(key, hi32(i)=0, lo32(i)=i);  bits32 = o0 ^ o1
// ---------------------------------------------------------------------------
__device__ __forceinline__ unsigned threefry_xor(unsigned x0, unsigned x1) {
    const unsigned ks0 = 0u;
    const unsigned ks1 = 42u;
    const unsigned ks2 = 0x1BD11BDAu ^ 0u ^ 42u;
    x0 += ks0; x1 += ks1;
#define TFR(r) { x0 += x1; x1 = __funnelshift_l(x1, x1, (r)); x1 ^= x0; }
    TFR(13) TFR(15) TFR(26) TFR(6)
    x0 += ks1; x1 += ks2 + 1u;
    TFR(17) TFR(29) TFR(16) TFR(24)
    x0 += ks2; x1 += ks0 + 2u;
    TFR(13) TFR(15) TFR(26) TFR(6)
    x0 += ks0; x1 += ks1 + 3u;
    TFR(17) TFR(29) TFR(16) TFR(24)
    x0 += ks1; x1 += ks2 + 4u;
    TFR(13) TFR(15) TFR(26) TFR(6)
    x0 += ks2; x1 += ks0 + 5u;
#undef TFR
    return x0 ^ x1;
}

__device__ __forceinline__ float u01(unsigned bits) {
    // jax.random.uniform: bitcast(bits>>9 | 0x3f800000) - 1.0
    return __uint_as_float((bits >> 9) | 0x3f800000u) - 1.0f;
}

// ---------------------------------------------------------------------------
// K1: tiny MLP.  grid(256), block(128).  Writes x transposed -> g_xT[h][b]
// ---------------------------------------------------------------------------
__global__ void mlp_kernel(const float* __restrict__ z,
                           const float* __restrict__ w0, const float* __restrict__ b0,
                           const float* __restrict__ gm0, const float* __restrict__ be0,
                           const float* __restrict__ m0, const float* __restrict__ v0,
                           const float* __restrict__ w1, const float* __restrict__ b1,
                           const float* __restrict__ gm1, const float* __restrict__ be1,
                           const float* __restrict__ m1, const float* __restrict__ v1) {
    __shared__ float zs[LATD];
    __shared__ float s0[HID];
    const int b = blockIdx.x, h = threadIdx.x;
    if (h < LATD) zs[h] = z[b * LATD + h];
    __syncthreads();
    float t = b0[h];
#pragma unroll
    for (int k = 0; k < LATD; k++) t = fmaf(zs[k], w0[k * HID + h], t);
    t = (t - m0[h]) * rsqrtf(v0[h] + 1e-3f) * gm0[h] + be0[h];
    s0[h] = fmaxf(t, 0.0f);
    __syncthreads();
    float t2 = b1[h];
#pragma unroll
    for (int k = 0; k < HID; k++) t2 = fmaf(s0[k], w1[k * HID + h], t2);
    t2 = (t2 - m1[h]) * rsqrtf(v1[h] + 1e-3f) * gm1[h] + be1[h];
    g_xT[h * BDIM + b] = fmaxf(t2, 0.0f);
}

// ---------------------------------------------------------------------------
// K2: C[256,N] = X[256,128] @ W[128,N] + bias, optional exp epilogue.
// Block: 256 threads, 64x64 tile, 4x4 per thread. W staged in 32KB smem,
// X (transposed) streamed from L1 (128KB total, fully resident).
// ---------------------------------------------------------------------------
template <int ACT>
__global__ void __launch_bounds__(256) gemm128(const float* __restrict__ W,
                                               const float* __restrict__ bias,
                                               float* __restrict__ out, int N) {
    __shared__ float Ws[128][64];
    const int tid = threadIdx.x;
    const int n0 = blockIdx.x * 64;
    const int m0 = blockIdx.y * 64;
#pragma unroll
    for (int t = 0; t < 8; t++) {
        int f = tid + t * 256;
        int k = f >> 4;
        int j4 = (f & 15) << 2;
        int n = n0 + j4;
        float4 v = make_float4(0.f, 0.f, 0.f, 0.f);
        if (n < N) v = *reinterpret_cast<const float4*>(W + (size_t)k * N + n);
        *reinterpret_cast<float4*>(&Ws[k][j4]) = v;
    }
    __syncthreads();
    const int tn = (tid & 15) << 2;
    const int tm = (tid >> 4) << 2;
    float acc[4][4] = {};
    const float* xb = g_xT + m0 + tm;
#pragma unroll 8
    for (int k = 0; k < 128; k++) {
        const float4 av = __ldg(reinterpret_cast<const float4*>(xb + (size_t)k * BDIM));
        const float4 bv = *reinterpret_cast<const float4*>(&Ws[k][tn]);
        const float a[4] = {av.x, av.y, av.z, av.w};
        const float bw[4] = {bv.x, bv.y, bv.z, bv.w};
#pragma unroll
        for (int i = 0; i < 4; i++)
#pragma unroll
            for (int j = 0; j < 4; j++) acc[i][j] = fmaf(a[i], bw[j], acc[i][j]);
    }
    const int n = n0 + tn;
    if (n < N) {
#pragma unroll
        for (int i = 0; i < 4; i++) {
            const int m = m0 + tm + i;
            float4 r;
            r.x = acc[i][0] + bias[n + 0];
            r.y = acc[i][1] + bias[n + 1];
            r.z = acc[i][2] + bias[n + 2];
            r.w = acc[i][3] + bias[n + 3];
            if (ACT == 1) { r.x = expf(r.x); r.y = expf(r.y); r.z = expf(r.z); r.w = expf(r.w); }
            *reinterpret_cast<float4*>(out + (size_t)m * N + n) = r;
        }
    }
}

// ---------------------------------------------------------------------------
// K3: softmax over the C=7 copy-number states, plus log(pi+eps)
// ---------------------------------------------------------------------------
__global__ void rho_softmax_kernel() {
    const int i = blockIdx.x * 256 + threadIdx.x;  // over B*GB = 256000
    if (i >= BDIM * GBD) return;
    float l[CDIM];
    float mx = -3.402823466e38f;
#pragma unroll
    for (int c = 0; c < CDIM; c++) {
        l[c] = g_rlog[c * (BDIM * GBD) + i];
        mx = fmaxf(mx, l[c]);
    }
    float s = 0.0f;
#pragma unroll
    for (int c = 0; c < CDIM; c++) { l[c] = expf(l[c] - mx); s += l[c]; }
#pragma unroll
    for (int c = 0; c < CDIM; c++) {
        const float p = l[c] / s;
        g_pi[i * CDIM + c] = p;
        g_lpi[i * CDIM + c] = logf(p + 1e-20f);
    }
}

// ---------------------------------------------------------------------------
// K4: Gumbel straight-through sampler (partitionable threefry).
// One thread per (b, g): 7 independent hashes, counter = linear idx in (B,G,C).
// ---------------------------------------------------------------------------
__global__ void __launch_bounds__(256) gumbel_kernel(const float* __restrict__ ws,
                                                     const float* __restrict__ bs,
                                                     float* __restrict__ out) {
    const int g = blockIdx.x * 256 + threadIdx.x;
    if (g >= GDIM) return;
    const int b = blockIdx.y;  // 0..255
    const int gb = g / 25;
    const int i0 = b * GBD + gb;
    const unsigned base = ((unsigned)b * (unsigned)GDIM + (unsigned)g) * 7u;

    float best = -3.402823466e38f;
    int amax = 0;
    float p[CDIM];
#pragma unroll
    for (int c = 0; c < CDIM; c++) {
        const unsigned bits = threefry_xor(0u, base + (unsigned)c);
        const float u = u01(bits);
        const float gn = -logf(-logf(u + 1e-20f) + 1e-20f);
        const float l = g_lpi[i0 * CDIM + c] + gn;
        if (l > best) { best = l; amax = c; }
        p[c] = g_pi[i0 * CDIM + c];
    }
    float* muo = out;
    float* smo = out + OFF_SAMP;
    float* pio = out + OFF_PI;
    const size_t e0 = (size_t)b * GDIM + g;
#pragma unroll
    for (int c = 0; c < CDIM; c++) pio[e0 * 7 + c] = p[c];
    const float s0 = (float)amax;
    smo[e0] = s0;
    muo[e0] = 1.0f / (1.0f + expf(-fmaf(s0, ws[g], bs[g])));
}

// ---------------------------------------------------------------------------
extern "C" void kernel_launch(void* const* d_in, const int* in_sizes, int n_in,
                              void* d_out, int out_size) {
    const float* z   = (const float*)d_in[0];
    const float* w0  = (const float*)d_in[1];
    const float* b0  = (const float*)d_in[2];
    const float* gm0 = (const float*)d_in[3];
    const float* be0 = (const float*)d_in[4];
    const float* m0  = (const float*)d_in[5];
    const float* v0  = (const float*)d_in[6];
    const float* w1  = (const float*)d_in[7];
    const float* b1  = (const float*)d_in[8];
    const float* gm1 = (const float*)d_in[9];
    const float* be1 = (const float*)d_in[10];
    const float* m1  = (const float*)d_in[11];
    const float* v1  = (const float*)d_in[12];
    const float* wr  = (const float*)d_in[13];
    const float* br  = (const float*)d_in[14];
    const float* wd  = (const float*)d_in[15];
    const float* bd  = (const float*)d_in[16];
    const float* wrho = (const float*)d_in[17];
    const float* brho = (const float*)d_in[18];
    const float* ws  = (const float*)d_in[19];
    const float* bs  = (const float*)d_in[20];
    float* out = (float*)d_out;

    float* rlog_ptr = nullptr;
    cudaGetSymbolAddress((void**)&rlog_ptr, g_rlog);

    mlp_kernel<<<BDIM, HID>>>(z, w0, b0, gm0, be0, m0, v0,
                              w1, b1, gm1, be1, m1, v1);

    // theta = exp(x@wr + br), pi_drop = x@wd + bd
    gemm128<1><<<dim3((GDIM + 63) / 64, 4), 256>>>(wr, br, out + OFF_THETA, GDIM);
    gemm128<0><<<dim3((GDIM + 63) / 64, 4), 256>>>(wd, bd, out + OFF_PDROP, GDIM);

    // rho logits: 7 heads of [256,1000]
    for (int c = 0; c < CDIM; c++)
        gemm128<0><<<dim3((GBD + 63) / 64, 4), 256>>>(
            wrho + (size_t)c * HID * GBD, brho + (size_t)c * GBD,
            rlog_ptr + (size_t)c * BDIM * GBD, GBD);

    rho_softmax_kernel<<<(BDIM * GBD + 255) / 256, 256>>>();

    gumbel_kernel<<<dim3((GDIM + 255) / 256, 256), 256>>>(ws, bs, out);
}

// round 4
// speedup vs baseline: 1.2130x; 1.2130x over previous
#include <cuda_runtime.h>
#include <cstdint>
#include <math.h>

#define BDIM 256
#define LATD 20
#define HID 128
#define GDIM 25000
#define CDIM 7
#define GBD 1000

// Output layout (float32, flattened tuple in order):
//   mu      [256,25000]    @ 0
//   theta   [256,25000]    @ 6400000
//   pi_drop [256,25000]    @ 12800000
//   sample  [256,25000]    @ 19200000
//   pi      [256,25000,7]  @ 25600000
#define OFF_THETA  6400000
#define OFF_PDROP 12800000
#define OFF_SAMP  19200000
#define OFF_PI    25600000

// Scratch (device globals: no allocation allowed)
__device__ float g_xT[HID * BDIM];          // x transposed: [h][b]
__device__ float g_rlog[CDIM * BDIM * GBD]; // rho logits [c][b][o]
__device__ float g_pi[BDIM * GBD * CDIM];   // softmax(rho) as [b][o][c]
__device__ float g_lpi[BDIM * GBD * CDIM];  // log(pi + 1e-20) as [b][o][c]

// Packed fp32x2 ops (sm_103a FFMA2 — only reachable via PTX)
#define FMA_F32X2(d, a, b, c) \
    asm("fma.rn.f32x2 %0, %1, %2, %3;" : "=l"(d) : "l"(a), "l"(b), "l"(c))
#define PACK_DUP_F32X2(d, s) \
    asm("mov.b64 %0, {%1, %1};" : "=l"(d) : "r"(__float_as_uint(s)))

// ---------------------------------------------------------------------------
// JAX threefry2x32, key = (0, 42), 20 rounds, partitionable mode:
//   bits32(i) = o0 ^ o1 where (o0,o1) = threefry(key, 0, i)
// ---------------------------------------------------------------------------
__device__ __forceinline__ unsigned threefry_xor(unsigned x0, unsigned x1) {
    const unsigned ks0 = 0u;
    const unsigned ks1 = 42u;
    const unsigned ks2 = 0x1BD11BDAu ^ 0u ^ 42u;
    x0 += ks0; x1 += ks1;
#define TFR(r) { x0 += x1; x1 = __funnelshift_l(x1, x1, (r)); x1 ^= x0; }
    TFR(13) TFR(15) TFR(26) TFR(6)
    x0 += ks1; x1 += ks2 + 1u;
    TFR(17) TFR(29) TFR(16) TFR(24)
    x0 += ks2; x1 += ks0 + 2u;
    TFR(13) TFR(15) TFR(26) TFR(6)
    x0 += ks0; x1 += ks1 + 3u;
    TFR(17) TFR(29) TFR(16) TFR(24)
    x0 += ks1; x1 += ks2 + 4u;
    TFR(13) TFR(15) TFR(26) TFR(6)
    x0 += ks2; x1 += ks0 + 5u;
#undef TFR
    return x0 ^ x1;
}

__device__ __forceinline__ float u01(unsigned bits) {
    return __uint_as_float((bits >> 9) | 0x3f800000u) - 1.0f;
}

// ---------------------------------------------------------------------------
// K1: tiny MLP.  grid(256), block(128).  Writes x transposed -> g_xT[h][b]
// ---------------------------------------------------------------------------
__global__ void mlp_kernel(const float* __restrict__ z,
                           const float* __restrict__ w0, const float* __restrict__ b0,
                           const float* __restrict__ gm0, const float* __restrict__ be0,
                           const float* __restrict__ m0, const float* __restrict__ v0,
                           const float* __restrict__ w1, const float* __restrict__ b1,
                           const float* __restrict__ gm1, const float* __restrict__ be1,
                           const float* __restrict__ m1, const float* __restrict__ v1) {
    __shared__ float zs[LATD];
    __shared__ float s0[HID];
    const int b = blockIdx.x, h = threadIdx.x;
    if (h < LATD) zs[h] = z[b * LATD + h];
    __syncthreads();
    float t = b0[h];
#pragma unroll
    for (int k = 0; k < LATD; k++) t = fmaf(zs[k], w0[k * HID + h], t);
    t = (t - m0[h]) * rsqrtf(v0[h] + 1e-3f) * gm0[h] + be0[h];
    s0[h] = fmaxf(t, 0.0f);
    __syncthreads();
    float t2 = b1[h];
#pragma unroll
    for (int k = 0; k < HID; k++) t2 = fmaf(s0[k], w1[k * HID + h], t2);
    t2 = (t2 - m1[h]) * rsqrtf(v1[h] + 1e-3f) * gm1[h] + be1[h];
    g_xT[h * BDIM + b] = fmaxf(t2, 0.0f);
}

// ---------------------------------------------------------------------------
// GEMM core: one 64x64 output tile of X[256,128] @ W[128,N] + bias.
// 256 threads, 4x4 per thread, inner products via packed f32x2 FMA.
// ---------------------------------------------------------------------------
template <int ACT>
__device__ __forceinline__ void gemm_tile(const float* __restrict__ W,
                                          const float* __restrict__ bias,
                                          float* __restrict__ out,
                                          int N, int n0, int m0) {
    __shared__ float Ws[128][64];
    const int tid = threadIdx.x;
#pragma unroll
    for (int t = 0; t < 8; t++) {
        int f = tid + t * 256;
        int k = f >> 4;
        int j4 = (f & 15) << 2;
        int n = n0 + j4;
        float4 v = make_float4(0.f, 0.f, 0.f, 0.f);
        if (n < N) v = *reinterpret_cast<const float4*>(W + (size_t)k * N + n);
        *reinterpret_cast<float4*>(&Ws[k][j4]) = v;
    }
    __syncthreads();
    const int tn = (tid & 15) << 2;
    const int tm = (tid >> 4) << 2;
    unsigned long long acc[4][2] = {};
    const float* xb = g_xT + m0 + tm;
#pragma unroll 4
    for (int k = 0; k < 128; k++) {
        const float4 av = __ldg(reinterpret_cast<const float4*>(xb + (size_t)k * BDIM));
        const unsigned long long* bp =
            reinterpret_cast<const unsigned long long*>(&Ws[k][tn]);
        const unsigned long long b01 = bp[0];
        const unsigned long long b23 = bp[1];
        const float a[4] = {av.x, av.y, av.z, av.w};
#pragma unroll
        for (int i = 0; i < 4; i++) {
            unsigned long long ap;
            PACK_DUP_F32X2(ap, a[i]);
            FMA_F32X2(acc[i][0], ap, b01, acc[i][0]);
            FMA_F32X2(acc[i][1], ap, b23, acc[i][1]);
        }
    }
    const int n = n0 + tn;
    if (n < N) {
        const float4 bv = *reinterpret_cast<const float4*>(bias + n);
#pragma unroll
        for (int i = 0; i < 4; i++) {
            const int m = m0 + tm + i;
            float2 lo = *reinterpret_cast<float2*>(&acc[i][0]);
            float2 hi = *reinterpret_cast<float2*>(&acc[i][1]);
            float4 r;
            r.x = lo.x + bv.x;
            r.y = lo.y + bv.y;
            r.z = hi.x + bv.z;
            r.w = hi.y + bv.w;
            if (ACT == 1) { r.x = expf(r.x); r.y = expf(r.y); r.z = expf(r.z); r.w = expf(r.w); }
            *reinterpret_cast<float4*>(out + (size_t)m * N + n) = r;
        }
    }
}

// K2a: theta (exp) + pi_drop in one launch. z=0 -> theta, z=1 -> pi_drop.
__global__ void __launch_bounds__(256) big_gemm_kernel(const float* __restrict__ wr,
                                                       const float* __restrict__ br,
                                                       const float* __restrict__ wd,
                                                       const float* __restrict__ bd,
                                                       float* __restrict__ out) {
    const int n0 = blockIdx.x * 64;
    const int m0 = blockIdx.y * 64;
    if (blockIdx.z == 0)
        gemm_tile<1>(wr, br, out + OFF_THETA, GDIM, n0, m0);
    else
        gemm_tile<0>(wd, bd, out + OFF_PDROP, GDIM, n0, m0);
}

// K2b: all 7 rho heads in one launch. z = copy-number state c.
__global__ void __launch_bounds__(256) rho_gemm_kernel(const float* __restrict__ wrho,
                                                       const float* __restrict__ brho,
                                                       float* __restrict__ rlog) {
    const int c = blockIdx.z;
    const int n0 = blockIdx.x * 64;
    const int m0 = blockIdx.y * 64;
    gemm_tile<0>(wrho + (size_t)c * HID * GBD, brho + (size_t)c * GBD,
                 rlog + (size_t)c * BDIM * GBD, GBD, n0, m0);
}

// ---------------------------------------------------------------------------
// K3: softmax over the C=7 copy-number states, plus log(pi+eps)
// ---------------------------------------------------------------------------
__global__ void rho_softmax_kernel() {
    const int i = blockIdx.x * 256 + threadIdx.x;  // over B*GB = 256000
    if (i >= BDIM * GBD) return;
    float l[CDIM];
    float mx = -3.402823466e38f;
#pragma unroll
    for (int c = 0; c < CDIM; c++) {
        l[c] = g_rlog[c * (BDIM * GBD) + i];
        mx = fmaxf(mx, l[c]);
    }
    float s = 0.0f;
#pragma unroll
    for (int c = 0; c < CDIM; c++) { l[c] = expf(l[c] - mx); s += l[c]; }
#pragma unroll
    for (int c = 0; c < CDIM; c++) {
        const float p = l[c] / s;
        g_pi[i * CDIM + c] = p;
        g_lpi[i * CDIM + c] = logf(p + 1e-20f);
    }
}

// ---------------------------------------------------------------------------
// K4: Gumbel straight-through sampler (partitionable threefry).
// ---------------------------------------------------------------------------
__global__ void __launch_bounds__(256) gumbel_kernel(const float* __restrict__ ws,
                                                     const float* __restrict__ bs,
                                                     float* __restrict__ out) {
    const int g = blockIdx.x * 256 + threadIdx.x;
    if (g >= GDIM) return;
    const int b = blockIdx.y;  // 0..255
    const int gb = g / 25;
    const int i0 = b * GBD + gb;
    const unsigned base = ((unsigned)b * (unsigned)GDIM + (unsigned)g) * 7u;

    float best = -3.402823466e38f;
    int amax = 0;
    float p[CDIM];
#pragma unroll
    for (int c = 0; c < CDIM; c++) {
        const unsigned bits = threefry_xor(0u, base + (unsigned)c);
        const float u = u01(bits);
        const float gn = -logf(-logf(u + 1e-20f) + 1e-20f);
        const float l = g_lpi[i0 * CDIM + c] + gn;
        if (l > best) { best = l; amax = c; }
        p[c] = g_pi[i0 * CDIM + c];
    }
    float* muo = out;
    float* smo = out + OFF_SAMP;
    float* pio = out + OFF_PI;
    const size_t e0 = (size_t)b * GDIM + g;
#pragma unroll
    for (int c = 0; c < CDIM; c++) pio[e0 * 7 + c] = p[c];
    const float s0 = (float)amax;
    smo[e0] = s0;
    muo[e0] = 1.0f / (1.0f + expf(-fmaf(s0, ws[g], bs[g])));
}

// ---------------------------------------------------------------------------
extern "C" void kernel_launch(void* const* d_in, const int* in_sizes, int n_in,
                              void* d_out, int out_size) {
    const float* z   = (const float*)d_in[0];
    const float* w0  = (const float*)d_in[1];
    const float* b0  = (const float*)d_in[2];
    const float* gm0 = (const float*)d_in[3];
    const float* be0 = (const float*)d_in[4];
    const float* m0  = (const float*)d_in[5];
    const float* v0  = (const float*)d_in[6];
    const float* w1  = (const float*)d_in[7];
    const float* b1  = (const float*)d_in[8];
    const float* gm1 = (const float*)d_in[9];
    const float* be1 = (const float*)d_in[10];
    const float* m1  = (const float*)d_in[11];
    const float* v1  = (const float*)d_in[12];
    const float* wr  = (const float*)d_in[13];
    const float* br  = (const float*)d_in[14];
    const float* wd  = (const float*)d_in[15];
    const float* bd  = (const float*)d_in[16];
    const float* wrho = (const float*)d_in[17];
    const float* brho = (const float*)d_in[18];
    const float* ws  = (const float*)d_in[19];
    const float* bs  = (const float*)d_in[20];
    float* out = (float*)d_out;

    float* rlog_ptr = nullptr;
    cudaGetSymbolAddress((void**)&rlog_ptr, g_rlog);

    mlp_kernel<<<BDIM, HID>>>(z, w0, b0, gm0, be0, m0, v0,
                              w1, b1, gm1, be1, m1, v1);

    // all 7 rho heads, one launch (448 blocks)
    rho_gemm_kernel<<<dim3((GBD + 63) / 64, 4, CDIM), 256>>>(wrho, brho, rlog_ptr);

    // theta + pi_drop, one launch (3128 blocks)
    big_gemm_kernel<<<dim3((GDIM + 63) / 64, 4, 2), 256>>>(wr, br, wd, bd, out);

    rho_softmax_kernel<<<(BDIM * GBD + 255) / 256, 256>>>();

    gumbel_kernel<<<dim3((GDIM + 255) / 256, 256), 256>>>(ws, bs, out);
}

// round 5
// speedup vs baseline: 1.3034x; 1.0745x over previous
#include <cuda_runtime.h>
#include <cstdint>
#include <math.h>

#define BDIM 256
#define LATD 20
#define HID 128
#define GDIM 25000
#define CDIM 7
#define GBD 1000
#define NS (BDIM * GBD)   // 256000 bins total

// Output layout (float32, flattened tuple in order):
//   mu      [256,25000]    @ 0
//   theta   [256,25000]    @ 6400000
//   pi_drop [256,25000]    @ 12800000
//   sample  [256,25000]    @ 19200000
//   pi      [256,25000,7]  @ 25600000
#define OFF_THETA  6400000
#define OFF_PDROP 12800000
#define OFF_SAMP  19200000
#define OFF_PI    25600000

// Scratch (device globals: no allocation allowed)
__device__ float g_xT[HID * BDIM];      // x transposed: [h][b]
__device__ float g_rlog[CDIM * NS];     // rho logits [c][b*GB]
__device__ float g_pi[CDIM * NS];       // softmax(rho), c-major [c][i]
__device__ float g_ipi[CDIM * NS];      // 1/(pi + 1e-20), c-major [c][i]

// Packed fp32x2 ops (sm_103a FFMA2 — only reachable via PTX)
#define FMA_F32X2(d, a, b, c) \
    asm("fma.rn.f32x2 %0, %1, %2, %3;" : "=l"(d) : "l"(a), "l"(b), "l"(c))
#define PACK_DUP_F32X2(d, s) \
    asm("mov.b64 %0, {%1, %1};" : "=l"(d) : "r"(__float_as_uint(s)))

// ---------------------------------------------------------------------------
// JAX threefry2x32, key = (0, 42), 20 rounds, partitionable mode:
//   bits32(i) = o0 ^ o1 where (o0,o1) = threefry(key, 0, i)
// ---------------------------------------------------------------------------
__device__ __forceinline__ unsigned threefry_xor(unsigned x0, unsigned x1) {
    const unsigned ks0 = 0u;
    const unsigned ks1 = 42u;
    const unsigned ks2 = 0x1BD11BDAu ^ 0u ^ 42u;
    x0 += ks0; x1 += ks1;
#define TFR(r) { x0 += x1; x1 = __funnelshift_l(x1, x1, (r)); x1 ^= x0; }
    TFR(13) TFR(15) TFR(26) TFR(6)
    x0 += ks1; x1 += ks2 + 1u;
    TFR(17) TFR(29) TFR(16) TFR(24)
    x0 += ks2; x1 += ks0 + 2u;
    TFR(13) TFR(15) TFR(26) TFR(6)
    x0 += ks0; x1 += ks1 + 3u;
    TFR(17) TFR(29) TFR(16) TFR(24)
    x0 += ks1; x1 += ks2 + 4u;
    TFR(13) TFR(15) TFR(26) TFR(6)
    x0 += ks2; x1 += ks0 + 5u;
#undef TFR
    return x0 ^ x1;
}

__device__ __forceinline__ float u01(unsigned bits) {
    return __uint_as_float((bits >> 9) | 0x3f800000u) - 1.0f;
}

// ---------------------------------------------------------------------------
// K1: tiny MLP.  grid(256), block(128).  Writes x transposed -> g_xT[h][b]
// ---------------------------------------------------------------------------
__global__ void mlp_kernel(const float* __restrict__ z,
                           const float* __restrict__ w0, const float* __restrict__ b0,
                           const float* __restrict__ gm0, const float* __restrict__ be0,
                           const float* __restrict__ m0, const float* __restrict__ v0,
                           const float* __restrict__ w1, const float* __restrict__ b1,
                           const float* __restrict__ gm1, const float* __restrict__ be1,
                           const float* __restrict__ m1, const float* __restrict__ v1) {
    __shared__ float zs[LATD];
    __shared__ float s0[HID];
    const int b = blockIdx.x, h = threadIdx.x;
    if (h < LATD) zs[h] = z[b * LATD + h];
    __syncthreads();
    float t = b0[h];
#pragma unroll
    for (int k = 0; k < LATD; k++) t = fmaf(zs[k], w0[k * HID + h], t);
    t = (t - m0[h]) * rsqrtf(v0[h] + 1e-3f) * gm0[h] + be0[h];
    s0[h] = fmaxf(t, 0.0f);
    __syncthreads();
    float t2 = b1[h];
#pragma unroll
    for (int k = 0; k < HID; k++) t2 = fmaf(s0[k], w1[k * HID + h], t2);
    t2 = (t2 - m1[h]) * rsqrtf(v1[h] + 1e-3f) * gm1[h] + be1[h];
    g_xT[h * BDIM + b] = fmaxf(t2, 0.0f);
}

// ---------------------------------------------------------------------------
// GEMM core: one 64x64 output tile of X[256,128] @ W[128,N] + bias.
// 256 threads, 4x4 per thread, inner products via packed f32x2 FMA.
// ---------------------------------------------------------------------------
template <int ACT>
__device__ __forceinline__ void gemm_tile(const float* __restrict__ W,
                                          const float* __restrict__ bias,
                                          float* __restrict__ out,
                                          int N, int n0, int m0) {
    __shared__ float Ws[128][64];
    const int tid = threadIdx.x;
#pragma unroll
    for (int t = 0; t < 8; t++) {
        int f = tid + t * 256;
        int k = f >> 4;
        int j4 = (f & 15) << 2;
        int n = n0 + j4;
        float4 v = make_float4(0.f, 0.f, 0.f, 0.f);
        if (n < N) v = *reinterpret_cast<const float4*>(W + (size_t)k * N + n);
        *reinterpret_cast<float4*>(&Ws[k][j4]) = v;
    }
    __syncthreads();
    const int tn = (tid & 15) << 2;
    const int tm = (tid >> 4) << 2;
    unsigned long long acc[4][2] = {};
    const float* xb = g_xT + m0 + tm;
#pragma unroll 4
    for (int k = 0; k < 128; k++) {
        const float4 av = __ldg(reinterpret_cast<const float4*>(xb + (size_t)k * BDIM));
        const unsigned long long* bp =
            reinterpret_cast<const unsigned long long*>(&Ws[k][tn]);
        const unsigned long long b01 = bp[0];
        const unsigned long long b23 = bp[1];
        const float a[4] = {av.x, av.y, av.z, av.w};
#pragma unroll
        for (int i = 0; i < 4; i++) {
            unsigned long long ap;
            PACK_DUP_F32X2(ap, a[i]);
            FMA_F32X2(acc[i][0], ap, b01, acc[i][0]);
            FMA_F32X2(acc[i][1], ap, b23, acc[i][1]);
        }
    }
    const int n = n0 + tn;
    if (n < N) {
        const float4 bv = *reinterpret_cast<const float4*>(bias + n);
#pragma unroll
        for (int i = 0; i < 4; i++) {
            const int m = m0 + tm + i;
            float2 lo = *reinterpret_cast<float2*>(&acc[i][0]);
            float2 hi = *reinterpret_cast<float2*>(&acc[i][1]);
            float4 r;
            r.x = lo.x + bv.x;
            r.y = lo.y + bv.y;
            r.z = hi.x + bv.z;
            r.w = hi.y + bv.w;
            if (ACT == 1) { r.x = expf(r.x); r.y = expf(r.y); r.z = expf(r.z); r.w = expf(r.w); }
            *reinterpret_cast<float4*>(out + (size_t)m * N + n) = r;
        }
    }
}

// K2a: theta (exp) + pi_drop in one launch. z=0 -> theta, z=1 -> pi_drop.
__global__ void __launch_bounds__(256) big_gemm_kernel(const float* __restrict__ wr,
                                                       const float* __restrict__ br,
                                                       const float* __restrict__ wd,
                                                       const float* __restrict__ bd,
                                                       float* __restrict__ out) {
    const int n0 = blockIdx.x * 64;
    const int m0 = blockIdx.y * 64;
    if (blockIdx.z == 0)
        gemm_tile<1>(wr, br, out + OFF_THETA, GDIM, n0, m0);
    else
        gemm_tile<0>(wd, bd, out + OFF_PDROP, GDIM, n0, m0);
}

// K2b: all 7 rho heads in one launch. z = copy-number state c.
__global__ void __launch_bounds__(256) rho_gemm_kernel(const float* __restrict__ wrho,
                                                       const float* __restrict__ brho,
                                                       float* __restrict__ rlog) {
    const int c = blockIdx.z;
    const int n0 = blockIdx.x * 64;
    const int m0 = blockIdx.y * 64;
    gemm_tile<0>(wrho + (size_t)c * HID * GBD, brho + (size_t)c * GBD,
                 rlog + (size_t)c * BDIM * GBD, GBD, n0, m0);
}

// ---------------------------------------------------------------------------
// K3: softmax over the C=7 copy-number states. Writes pi and 1/(pi+eps),
// both c-major [c][i] for fully coalesced stores.
// ---------------------------------------------------------------------------
__global__ void rho_softmax_kernel() {
    const int i = blockIdx.x * 256 + threadIdx.x;  // over B*GB = 256000
    if (i >= NS) return;
    float l[CDIM];
    float mx = -3.402823466e38f;
#pragma unroll
    for (int c = 0; c < CDIM; c++) {
        l[c] = g_rlog[c * NS + i];
        mx = fmaxf(mx, l[c]);
    }
    float s = 0.0f;
#pragma unroll
    for (int c = 0; c < CDIM; c++) { l[c] = expf(l[c] - mx); s += l[c]; }
    const float inv_s = 1.0f / s;
#pragma unroll
    for (int c = 0; c < CDIM; c++) {
        const float p = l[c] * inv_s * s * (1.0f / s);  // placeholder-free exact p
        // NOTE: keep exact division semantics for p (matches ref l[c]/s):
        const float pe = l[c] / s;
        g_pi[c * NS + i] = pe;
        g_ipi[c * NS + i] = 1.0f / (pe + 1e-20f);
        (void)p;
    }
}

// ---------------------------------------------------------------------------
// K4: Gumbel straight-through sampler (partitionable threefry).
// Fast path: argmin_c nl_c * ipi_c  (monotone-equivalent to ref's argmax of
// log(pi+eps) - log(nl)).  If top-2 gap < 1e-5 rel, recompute with the exact
// reference log formula to guarantee identical ordering decisions.
// ---------------------------------------------------------------------------
__global__ void __launch_bounds__(256) gumbel_kernel(const float* __restrict__ ws,
                                                     const float* __restrict__ bs,
                                                     float* __restrict__ out) {
    const int g = blockIdx.x * 256 + threadIdx.x;
    if (g >= GDIM) return;
    const int b = blockIdx.y;  // 0..255
    const int gb = g / 25;
    const int i0 = b * GBD + gb;
    const unsigned base = ((unsigned)b * (unsigned)GDIM + (unsigned)g) * 7u;

    float nl[CDIM], p[CDIM];
    float w1 = 3.402823466e38f, w2 = 3.402823466e38f;
    int amin = 0;
#pragma unroll
    for (int c = 0; c < CDIM; c++) {
        const unsigned bits = threefry_xor(0u, base + (unsigned)c);
        const float u = u01(bits);
        nl[c] = -logf(u + 1e-20f) + 1e-20f;       // ref inner: -log(u+eps)+eps
        p[c] = g_pi[c * NS + i0];
        const float w = nl[c] * g_ipi[c * NS + i0];
        if (w < w1) { w2 = w1; w1 = w; amin = c; }
        else if (w < w2) { w2 = w; }
    }
    if (w2 - w1 < 1e-5f * w1) {
        // exact reference-formula ordering for near-ties
        float best = -3.402823466e38f;
        amin = 0;
#pragma unroll
        for (int c = 0; c < CDIM; c++) {
            const float l = logf(p[c] + 1e-20f) - logf(nl[c]);
            if (l > best) { best = l; amin = c; }
        }
    }

    float* muo = out;
    float* smo = out + OFF_SAMP;
    float* pio = out + OFF_PI;
    const size_t e0 = (size_t)b * GDIM + g;
#pragma unroll
    for (int c = 0; c < CDIM; c++) pio[e0 * 7 + c] = p[c];
    const float s0 = (float)amin;
    smo[e0] = s0;
    muo[e0] = 1.0f / (1.0f + expf(-fmaf(s0, ws[g], bs[g])));
}

// ---------------------------------------------------------------------------
extern "C" void kernel_launch(void* const* d_in, const int* in_sizes, int n_in,
                              void* d_out, int out_size) {
    const float* z   = (const float*)d_in[0];
    const float* w0  = (const float*)d_in[1];
    const float* b0  = (const float*)d_in[2];
    const float* gm0 = (const float*)d_in[3];
    const float* be0 = (const float*)d_in[4];
    const float* m0  = (const float*)d_in[5];
    const float* v0  = (const float*)d_in[6];
    const float* w1  = (const float*)d_in[7];
    const float* b1  = (const float*)d_in[8];
    const float* gm1 = (const float*)d_in[9];
    const float* be1 = (const float*)d_in[10];
    const float* m1  = (const float*)d_in[11];
    const float* v1  = (const float*)d_in[12];
    const float* wr  = (const float*)d_in[13];
    const float* br  = (const float*)d_in[14];
    const float* wd  = (const float*)d_in[15];
    const float* bd  = (const float*)d_in[16];
    const float* wrho = (const float*)d_in[17];
    const float* brho = (const float*)d_in[18];
    const float* ws  = (const float*)d_in[19];
    const float* bs  = (const float*)d_in[20];
    float* out = (float*)d_out;

    float* rlog_ptr = nullptr;
    cudaGetSymbolAddress((void**)&rlog_ptr, g_rlog);

    mlp_kernel<<<BDIM, HID>>>(z, w0, b0, gm0, be0, m0, v0,
                              w1, b1, gm1, be1, m1, v1);

    // all 7 rho heads, one launch (448 blocks)
    rho_gemm_kernel<<<dim3((GBD + 63) / 64, 4, CDIM), 256>>>(wrho, brho, rlog_ptr);

    // theta + pi_drop, one launch (3128 blocks)
    big_gemm_kernel<<<dim3((GDIM + 63) / 64, 4, 2), 256>>>(wr, br, wd, bd, out);

    rho_softmax_kernel<<<(NS + 255) / 256, 256>>>();

    gumbel_kernel<<<dim3((GDIM + 255) / 256, 256), 256>>>(ws, bs, out);
}

// round 6
// speedup vs baseline: 1.4149x; 1.0855x over previous
#include <cuda_runtime.h>
#include <cstdint>
#include <math.h>

#define BDIM 256
#define LATD 20
#define HID 128
#define GDIM 25000
#define CDIM 7
#define GBD 1000
#define NS (BDIM * GBD)   // 256000 bins total

// Output layout (float32, flattened tuple in order):
//   mu      [256,25000]    @ 0
//   theta   [256,25000]    @ 6400000
//   pi_drop [256,25000]    @ 12800000
//   sample  [256,25000]    @ 19200000
//   pi      [256,25000,7]  @ 25600000
#define OFF_THETA  6400000
#define OFF_PDROP 12800000
#define OFF_SAMP  19200000
#define OFF_PI    25600000

// Scratch (device globals: no allocation allowed)
__device__ float g_xT[HID * BDIM];      // x transposed: [h][b]
__device__ float g_rlog[CDIM * NS];     // rho logits [c][b*GB]
__device__ float g_pi[CDIM * NS];       // softmax(rho), c-major [c][i]
__device__ float g_ipi[CDIM * NS];      // 1/(pi + 1e-20), c-major [c][i]

// Packed fp32x2 ops (sm_103a FFMA2 — only reachable via PTX)
#define FMA_F32X2(d, a, b, c) \
    asm("fma.rn.f32x2 %0, %1, %2, %3;" : "=l"(d) : "l"(a), "l"(b), "l"(c))
#define PACK_DUP_F32X2(d, s) \
    asm("mov.b64 %0, {%1, %1};" : "=l"(d) : "r"(__float_as_uint(s)))

// ---------------------------------------------------------------------------
// JAX threefry2x32, key = (0, 42), 20 rounds, partitionable mode:
//   bits32(i) = o0 ^ o1 where (o0,o1) = threefry(key, 0, i)
// ---------------------------------------------------------------------------
__device__ __forceinline__ unsigned threefry_xor(unsigned x0, unsigned x1) {
    const unsigned ks0 = 0u;
    const unsigned ks1 = 42u;
    const unsigned ks2 = 0x1BD11BDAu ^ 0u ^ 42u;
    x0 += ks0; x1 += ks1;
#define TFR(r) { x0 += x1; x1 = __funnelshift_l(x1, x1, (r)); x1 ^= x0; }
    TFR(13) TFR(15) TFR(26) TFR(6)
    x0 += ks1; x1 += ks2 + 1u;
    TFR(17) TFR(29) TFR(16) TFR(24)
    x0 += ks2; x1 += ks0 + 2u;
    TFR(13) TFR(15) TFR(26) TFR(6)
    x0 += ks0; x1 += ks1 + 3u;
    TFR(17) TFR(29) TFR(16) TFR(24)
    x0 += ks1; x1 += ks2 + 4u;
    TFR(13) TFR(15) TFR(26) TFR(6)
    x0 += ks2; x1 += ks0 + 5u;
#undef TFR
    return x0 ^ x1;
}

__device__ __forceinline__ float u01(unsigned bits) {
    return __uint_as_float((bits >> 9) | 0x3f800000u) - 1.0f;
}

// ---------------------------------------------------------------------------
// K1: tiny MLP.  grid(256), block(128).  Writes x transposed -> g_xT[h][b]
// ---------------------------------------------------------------------------
__global__ void mlp_kernel(const float* __restrict__ z,
                           const float* __restrict__ w0, const float* __restrict__ b0,
                           const float* __restrict__ gm0, const float* __restrict__ be0,
                           const float* __restrict__ m0, const float* __restrict__ v0,
                           const float* __restrict__ w1, const float* __restrict__ b1,
                           const float* __restrict__ gm1, const float* __restrict__ be1,
                           const float* __restrict__ m1, const float* __restrict__ v1) {
    __shared__ float zs[LATD];
    __shared__ float s0[HID];
    const int b = blockIdx.x, h = threadIdx.x;
    if (h < LATD) zs[h] = z[b * LATD + h];
    __syncthreads();
    float t = b0[h];
#pragma unroll
    for (int k = 0; k < LATD; k++) t = fmaf(zs[k], w0[k * HID + h], t);
    t = (t - m0[h]) * rsqrtf(v0[h] + 1e-3f) * gm0[h] + be0[h];
    s0[h] = fmaxf(t, 0.0f);
    __syncthreads();
    float t2 = b1[h];
#pragma unroll
    for (int k = 0; k < HID; k++) t2 = fmaf(s0[k], w1[k * HID + h], t2);
    t2 = (t2 - m1[h]) * rsqrtf(v1[h] + 1e-3f) * gm1[h] + be1[h];
    g_xT[h * BDIM + b] = fmaxf(t2, 0.0f);
}

// ---------------------------------------------------------------------------
// GEMM core: one 64x64 output tile of X[256,128] @ W[128,N] + bias.
// 256 threads, 4x4 per thread, inner products via packed f32x2 FMA.
// ACT=1: theta epilogue uses __expf (smooth output, err ~1e-6 << 1e-3).
// ---------------------------------------------------------------------------
template <int ACT>
__device__ __forceinline__ void gemm_tile(const float* __restrict__ W,
                                          const float* __restrict__ bias,
                                          float* __restrict__ out,
                                          int N, int n0, int m0) {
    __shared__ float Ws[128][64];
    const int tid = threadIdx.x;
#pragma unroll
    for (int t = 0; t < 8; t++) {
        int f = tid + t * 256;
        int k = f >> 4;
        int j4 = (f & 15) << 2;
        int n = n0 + j4;
        float4 v = make_float4(0.f, 0.f, 0.f, 0.f);
        if (n < N) v = *reinterpret_cast<const float4*>(W + (size_t)k * N + n);
        *reinterpret_cast<float4*>(&Ws[k][j4]) = v;
    }
    __syncthreads();
    const int tn = (tid & 15) << 2;
    const int tm = (tid >> 4) << 2;
    unsigned long long acc[4][2] = {};
    const float* xb = g_xT + m0 + tm;
#pragma unroll 4
    for (int k = 0; k < 128; k++) {
        const float4 av = __ldg(reinterpret_cast<const float4*>(xb + (size_t)k * BDIM));
        const unsigned long long* bp =
            reinterpret_cast<const unsigned long long*>(&Ws[k][tn]);
        const unsigned long long b01 = bp[0];
        const unsigned long long b23 = bp[1];
        const float a[4] = {av.x, av.y, av.z, av.w};
#pragma unroll
        for (int i = 0; i < 4; i++) {
            unsigned long long ap;
            PACK_DUP_F32X2(ap, a[i]);
            FMA_F32X2(acc[i][0], ap, b01, acc[i][0]);
            FMA_F32X2(acc[i][1], ap, b23, acc[i][1]);
        }
    }
    const int n = n0 + tn;
    if (n < N) {
        const float4 bv = *reinterpret_cast<const float4*>(bias + n);
#pragma unroll
        for (int i = 0; i < 4; i++) {
            const int m = m0 + tm + i;
            float2 lo = *reinterpret_cast<float2*>(&acc[i][0]);
            float2 hi = *reinterpret_cast<float2*>(&acc[i][1]);
            float4 r;
            r.x = lo.x + bv.x;
            r.y = lo.y + bv.y;
            r.z = hi.x + bv.z;
            r.w = hi.y + bv.w;
            if (ACT == 1) {
                r.x = __expf(r.x); r.y = __expf(r.y);
                r.z = __expf(r.z); r.w = __expf(r.w);
            }
            *reinterpret_cast<float4*>(out + (size_t)m * N + n) = r;
        }
    }
}

// K2a: theta (exp) + pi_drop in one launch. z=0 -> theta, z=1 -> pi_drop.
__global__ void __launch_bounds__(256) big_gemm_kernel(const float* __restrict__ wr,
                                                       const float* __restrict__ br,
                                                       const float* __restrict__ wd,
                                                       const float* __restrict__ bd,
                                                       float* __restrict__ out) {
    const int n0 = blockIdx.x * 64;
    const int m0 = blockIdx.y * 64;
    if (blockIdx.z == 0)
        gemm_tile<1>(wr, br, out + OFF_THETA, GDIM, n0, m0);
    else
        gemm_tile<0>(wd, bd, out + OFF_PDROP, GDIM, n0, m0);
}

// K2b: all 7 rho heads in one launch. z = copy-number state c.
__global__ void __launch_bounds__(256) rho_gemm_kernel(const float* __restrict__ wrho,
                                                       const float* __restrict__ brho,
                                                       float* __restrict__ rlog) {
    const int c = blockIdx.z;
    const int n0 = blockIdx.x * 64;
    const int m0 = blockIdx.y * 64;
    gemm_tile<0>(wrho + (size_t)c * HID * GBD, brho + (size_t)c * GBD,
                 rlog + (size_t)c * BDIM * GBD, GBD, n0, m0);
}

// ---------------------------------------------------------------------------
// K3: softmax over the C=7 copy-number states. Accurate expf (pi feeds the
// sampler's ordering with no fallback protection). Writes pi and 1/(pi+eps),
// both c-major [c][i] for fully coalesced stores.
// ---------------------------------------------------------------------------
__global__ void rho_softmax_kernel() {
    const int i = blockIdx.x * 256 + threadIdx.x;  // over B*GB = 256000
    if (i >= NS) return;
    float l[CDIM];
    float mx = -3.402823466e38f;
#pragma unroll
    for (int c = 0; c < CDIM; c++) {
        l[c] = g_rlog[c * NS + i];
        mx = fmaxf(mx, l[c]);
    }
    float s = 0.0f;
#pragma unroll
    for (int c = 0; c < CDIM; c++) { l[c] = expf(l[c] - mx); s += l[c]; }
#pragma unroll
    for (int c = 0; c < CDIM; c++) {
        const float pe = l[c] / s;
        g_pi[c * NS + i] = pe;
        g_ipi[c * NS + i] = 1.0f / (pe + 1e-20f);
    }
}

// ---------------------------------------------------------------------------
// K4: Gumbel straight-through sampler. 2 adjacent genes per thread.
// Fast path: argmin_c nl_c * ipi_c with nl via MUFU __logf (off the fma pipe).
// Robust fallback: if top-2 gap < 1e-4*w2 + 4e-6 (>=20x worst-case __logf
// error with ipi<=~8), redo ordering with the exact accurate-logf reference
// formula — bitwise identical decisions to the reference.
// ---------------------------------------------------------------------------
__global__ void __launch_bounds__(256) gumbel_kernel(const float* __restrict__ ws,
                                                     const float* __restrict__ bs,
                                                     float* __restrict__ out) {
    const int t = blockIdx.x * 256 + threadIdx.x;
    const int g0 = t * 2;
    if (g0 >= GDIM) return;
    const int b = blockIdx.y;  // 0..255
    const size_t e0 = (size_t)b * GDIM + g0;

    float pbuf[2][CDIM];
    float sm[2];
#pragma unroll
    for (int q = 0; q < 2; q++) {
        const int g = g0 + q;
        const int i0 = b * GBD + g / 25;
        const unsigned base = ((unsigned)b * (unsigned)GDIM + (unsigned)g) * 7u;
        float u[CDIM];
        float w1 = 3.402823466e38f, w2 = 3.402823466e38f;
        int amin = 0;
#pragma unroll
        for (int c = 0; c < CDIM; c++) {
            const unsigned bits = threefry_xor(0u, base + (unsigned)c);
            u[c] = u01(bits);
            pbuf[q][c] = g_pi[c * NS + i0];
            const float nlf = -__logf(u[c] + 1e-20f);
            const float w = nlf * g_ipi[c * NS + i0];
            if (w < w1) { w2 = w1; w1 = w; amin = c; }
            else if (w < w2) { w2 = w; }
        }
        if (w2 - w1 < 1e-4f * w2 + 4e-6f) {
            // exact reference-formula ordering (accurate logf) for near-ties
            float best = -3.402823466e38f;
            amin = 0;
#pragma unroll
            for (int c = 0; c < CDIM; c++) {
                const float nle = -logf(u[c] + 1e-20f) + 1e-20f;
                const float l = logf(pbuf[q][c] + 1e-20f) - logf(nle);
                if (l > best) { best = l; amin = c; }
            }
        }
        sm[q] = (float)amin;
    }

    // pi: 14 contiguous floats (genes g0, g0+1), 8B-aligned -> 7 x STG.64
    float* pio = out + OFF_PI + e0 * 7;
#pragma unroll
    for (int j = 0; j < 7; j++) {
        float2 v;
        v.x = (j < 3 || (j == 3)) ? 0.f : 0.f;  // placeholder, overwritten below
        const int idx0 = 2 * j;
        const int idx1 = 2 * j + 1;
        v.x = (idx0 < 7) ? pbuf[0][idx0] : pbuf[1][idx0 - 7];
        v.y = (idx1 < 7) ? pbuf[0][idx1] : pbuf[1][idx1 - 7];
        *reinterpret_cast<float2*>(pio + idx0) = v;
    }

    const float2 wsv = *reinterpret_cast<const float2*>(ws + g0);
    const float2 bsv = *reinterpret_cast<const float2*>(bs + g0);
    float2 smv = make_float2(sm[0], sm[1]);
    *reinterpret_cast<float2*>(out + OFF_SAMP + e0) = smv;
    float2 muv;
    muv.x = 1.0f / (1.0f + __expf(-fmaf(sm[0], wsv.x, bsv.x)));
    muv.y = 1.0f / (1.0f + __expf(-fmaf(sm[1], wsv.y, bsv.y)));
    *reinterpret_cast<float2*>(out + e0) = muv;
}

// ---------------------------------------------------------------------------
extern "C" void kernel_launch(void* const* d_in, const int* in_sizes, int n_in,
                              void* d_out, int out_size) {
    const float* z   = (const float*)d_in[0];
    const float* w0  = (const float*)d_in[1];
    const float* b0  = (const float*)d_in[2];
    const float* gm0 = (const float*)d_in[3];
    const float* be0 = (const float*)d_in[4];
    const float* m0  = (const float*)d_in[5];
    const float* v0  = (const float*)d_in[6];
    const float* w1  = (const float*)d_in[7];
    const float* b1  = (const float*)d_in[8];
    const float* gm1 = (const float*)d_in[9];
    const float* be1 = (const float*)d_in[10];
    const float* m1  = (const float*)d_in[11];
    const float* v1  = (const float*)d_in[12];
    const float* wr  = (const float*)d_in[13];
    const float* br  = (const float*)d_in[14];
    const float* wd  = (const float*)d_in[15];
    const float* bd  = (const float*)d_in[16];
    const float* wrho = (const float*)d_in[17];
    const float* brho = (const float*)d_in[18];
    const float* ws  = (const float*)d_in[19];
    const float* bs  = (const float*)d_in[20];
    float* out = (float*)d_out;

    float* rlog_ptr = nullptr;
    cudaGetSymbolAddress((void**)&rlog_ptr, g_rlog);

    mlp_kernel<<<BDIM, HID>>>(z, w0, b0, gm0, be0, m0, v0,
                              w1, b1, gm1, be1, m1, v1);

    // all 7 rho heads, one launch (448 blocks)
    rho_gemm_kernel<<<dim3((GBD + 63) / 64, 4, CDIM), 256>>>(wrho, brho, rlog_ptr);

    // theta + pi_drop, one launch (3128 blocks)
    big_gemm_kernel<<<dim3((GDIM + 63) / 64, 4, 2), 256>>>(wr, br, wd, bd, out);

    rho_softmax_kernel<<<(NS + 255) / 256, 256>>>();

    // 2 genes per thread: 12500 threads per batch row
    gumbel_kernel<<<dim3((GDIM / 2 + 255) / 256, 256), 256>>>(ws, bs, out);
}